// round 2
// baseline (speedup 1.0000x reference)
#include <cuda_runtime.h>
#include <math.h>

#define BSZ   4
#define NTOK  1024
#define DIN   384
#define SST   16
#define NROWS 4096          // BSZ*NTOK
#define NCOLS 816           // 384 dt_s + 384 dt_d + 16 B + 16 Cr + 16 Ci
#define COLS_PAD 832        // padded to 13*64

// ---------------- static device scratch (no runtime allocation) ----------------
__device__ __align__(16) float g_wpack[DIN * COLS_PAD];    // [k][col]  1.28 MB
__device__ __align__(16) float g_bias[COLS_PAD];
__device__ __align__(16) float g_xT[DIN * NROWS];          // [d][b*1024+n] 6.3 MB
__device__ __align__(16) float g_scratch[COLS_PAD * NROWS];// [col][b*1024+n] 13.6 MB

__device__ __forceinline__ float softplusf(float z) {
    return (z > 20.f) ? z : log1pf(expf(z));
}

// ---------------- kernel 0a: pack weights k-major + bias ----------------
__global__ void pack_kernel(const float* __restrict__ dtsW, const float* __restrict__ dtsb,
                            const float* __restrict__ dtdW, const float* __restrict__ dtdb,
                            const float* __restrict__ BW,   const float* __restrict__ CrW,
                            const float* __restrict__ CiW) {
    int i = blockIdx.x * blockDim.x + threadIdx.x;
    if (i >= DIN * COLS_PAD) return;
    int k = i / COLS_PAD;
    int c = i % COLS_PAD;
    float v = 0.f;
    if      (c < 384) v = dtsW[c * DIN + k];            // row c of dt_self_W (x@W^T)
    else if (c < 768) v = dtdW[(c - 384) * DIN + k];
    else if (c < 784) v = BW [k * SST + (c - 768)];
    else if (c < 800) v = CrW[k * SST + (c - 784)];
    else if (c < 816) v = CiW[k * SST + (c - 800)];
    g_wpack[i] = v;
    if (k == 0) {
        float bv = 0.f;
        if (c < 384)      bv = dtsb[c];
        else if (c < 768) bv = dtdb[c - 384];
        g_bias[c] = bv;
    }
}

// ---------------- kernel 0b: transpose x -> xT[d][row] ----------------
__global__ void transpose_x(const float* __restrict__ x) {
    __shared__ float tile[32][33];
    int kb = blockIdx.x * 32;   // d base
    int rb = blockIdx.y * 32;   // row base
    int tx = threadIdx.x, ty = threadIdx.y;   // 32 x 8
    #pragma unroll
    for (int i = ty; i < 32; i += 8)
        tile[i][tx] = x[(rb + i) * DIN + kb + tx];
    __syncthreads();
    #pragma unroll
    for (int i = ty; i < 32; i += 8)
        g_xT[(kb + i) * NROWS + rb + tx] = tile[tx][i];
}

// ---------------- kernel 1: fused GEMM  out[c][r] = sum_k wpack[k][c] * xT[k][r] ----------------
// Tile: 64 cols x 128 rows x 16 k. 256 threads, each thread 4 cols x 8 rows.
#define GBM 64
#define GBN 128
#define GBK 16
__global__ __launch_bounds__(256) void gemm_kernel() {
    __shared__ float Ws[GBK][68];        // 16 x 64 (+pad)
    __shared__ float Xs[GBK][GBN + 4];   // 16 x 128 (+pad)
    int tid = threadIdx.x;
    int tx = tid & 15;        // row group: rows tx*4..+3 and 64+tx*4..+3
    int ty = tid >> 4;        // col group: cols ty*4..+3
    int cBase = blockIdx.x * GBM;
    int rBase = blockIdx.y * GBN;

    float acc[4][8];
    #pragma unroll
    for (int i = 0; i < 4; i++)
        #pragma unroll
        for (int j = 0; j < 8; j++) acc[i][j] = 0.f;

    for (int kB = 0; kB < DIN; kB += GBK) {
        {   // load W tile: 16x64, one float4 per thread
            int kk = tid >> 4, cc = (tid & 15) * 4;
            float4 v = *(const float4*)&g_wpack[(kB + kk) * COLS_PAD + cBase + cc];
            *(float4*)&Ws[kk][cc] = v;
        }
        #pragma unroll
        for (int ch = 0; ch < 2; ch++) {   // load X tile: 16x128, two float4 per thread
            int idx = tid + ch * 256;
            int kk = idx >> 5, rr = (idx & 31) * 4;
            float4 v = *(const float4*)&g_xT[(kB + kk) * NROWS + rBase + rr];
            *(float4*)&Xs[kk][rr] = v;
        }
        __syncthreads();
        #pragma unroll
        for (int kk = 0; kk < GBK; kk++) {
            float a[4], b[8];
            *(float4*)&a[0] = *(const float4*)&Ws[kk][ty * 4];
            *(float4*)&b[0] = *(const float4*)&Xs[kk][tx * 4];
            *(float4*)&b[4] = *(const float4*)&Xs[kk][64 + tx * 4];
            #pragma unroll
            for (int i = 0; i < 4; i++)
                #pragma unroll
                for (int j = 0; j < 8; j++)
                    acc[i][j] = fmaf(a[i], b[j], acc[i][j]);
        }
        __syncthreads();
    }

    // epilogue: activation for dt columns, transposed (col-major over rows) store
    #pragma unroll
    for (int i = 0; i < 4; i++) {
        int c = cBase + ty * 4 + i;
        float bv = g_bias[c];
        bool act = (c < 768);
        float o[8];
        #pragma unroll
        for (int j = 0; j < 8; j++) {
            float v = acc[i][j];
            if (act) v = fminf(softplusf(v + bv), 0.15f);
            o[j] = v;
        }
        *(float4*)&g_scratch[c * NROWS + rBase + tx * 4]      = *(float4*)&o[0];
        *(float4*)&g_scratch[c * NROWS + rBase + 64 + tx * 4] = *(float4*)&o[4];
    }
}

// ---------------- kernel 2: per-(b,d) SSM evolution over 32x32 grid, loop s ----------------
// 256 threads; thread owns 1x4 row segment. h in registers, shared = stencil exchange.
// Shared stride 37 (odd) => bank-conflict-free 9-tap reads and interior stores.
#define SH_STRIDE 37
__global__ __launch_bounds__(256) void ssm_kernel(const float* __restrict__ conv_w,
                                                  const float* __restrict__ ralpha,
                                                  const float* __restrict__ rbeta,
                                                  const float* __restrict__ Dparam,
                                                  const float* __restrict__ A_log,
                                                  float* __restrict__ y) {
    __shared__ float shR[34 * SH_STRIDE];
    __shared__ float shI[34 * SH_STRIDE];

    int d = blockIdx.x;
    int b = blockIdx.y;
    int tid = threadIdx.x;
    int pr  = tid >> 3;          // pixel row 0..31
    int pcb = (tid & 7) * 4;     // pixel col base 0,4,...,28
    int nbase = pr * 32 + pcb;
    int row0 = b * NTOK;

    // conv weights / scalars
    float w[9];
    #pragma unroll
    for (int i = 0; i < 9; i++) w[i] = conv_w[d * 9 + i];
    float alpha = ralpha[d];
    float beta  = rbeta[d];
    float Dp    = Dparam[d];

    // per-pixel inputs (all coalesced float4)
    float xv[4], ds[4], dd[4], yacc[4];
    {
        float4 t;
        t = *(const float4*)&g_xT[d * NROWS + row0 + nbase];
        xv[0]=t.x; xv[1]=t.y; xv[2]=t.z; xv[3]=t.w;
        t = *(const float4*)&g_scratch[d * NROWS + row0 + nbase];
        ds[0]=t.x; ds[1]=t.y; ds[2]=t.z; ds[3]=t.w;
        t = *(const float4*)&g_scratch[(384 + d) * NROWS + row0 + nbase];
        dd[0]=t.x; dd[1]=t.y; dd[2]=t.z; dd[3]=t.w;
    }
    #pragma unroll
    for (int j = 0; j < 4; j++) yacc[j] = xv[j] * Dp;

    for (int s = 0; s < SST; s++) {
        float A = -softplusf(A_log[d * SST + s]);
        float u[4], hr[4], hi[4];
        {
            float4 t = *(const float4*)&g_scratch[(768 + s) * NROWS + row0 + nbase];
            u[0]=xv[0]*t.x; u[1]=xv[1]*t.y; u[2]=xv[2]*t.z; u[3]=xv[3]*t.w;
        }
        #pragma unroll
        for (int j = 0; j < 4; j++) { hr[j] = u[j]; hi[j] = 0.f; }

        #pragma unroll
        for (int step = 0; step < 2; step++) {
            // 1. publish h snapshot to shared (interior at +1,+1)
            #pragma unroll
            for (int j = 0; j < 4; j++) {
                int off = (pr + 1) * SH_STRIDE + pcb + 1 + j;
                shR[off] = hr[j];
                shI[off] = hi[j];
            }
            __syncthreads();
            // 2. replicate-pad halo
            if (tid < 32) {
                int c = tid;
                shR[0 * SH_STRIDE + c + 1]  = shR[1 * SH_STRIDE + c + 1];
                shR[33 * SH_STRIDE + c + 1] = shR[32 * SH_STRIDE + c + 1];
                shR[(c + 1) * SH_STRIDE + 0]  = shR[(c + 1) * SH_STRIDE + 1];
                shR[(c + 1) * SH_STRIDE + 33] = shR[(c + 1) * SH_STRIDE + 32];
                shI[0 * SH_STRIDE + c + 1]  = shI[1 * SH_STRIDE + c + 1];
                shI[33 * SH_STRIDE + c + 1] = shI[32 * SH_STRIDE + c + 1];
                shI[(c + 1) * SH_STRIDE + 0]  = shI[(c + 1) * SH_STRIDE + 1];
                shI[(c + 1) * SH_STRIDE + 33] = shI[(c + 1) * SH_STRIDE + 32];
                if (tid == 0) {
                    shR[0]                        = shR[1 * SH_STRIDE + 1];
                    shR[33]                       = shR[1 * SH_STRIDE + 32];
                    shR[33 * SH_STRIDE + 0]       = shR[32 * SH_STRIDE + 1];
                    shR[33 * SH_STRIDE + 33]      = shR[32 * SH_STRIDE + 32];
                    shI[0]                        = shI[1 * SH_STRIDE + 1];
                    shI[33]                       = shI[1 * SH_STRIDE + 32];
                    shI[33 * SH_STRIDE + 0]       = shI[32 * SH_STRIDE + 1];
                    shI[33 * SH_STRIDE + 33]      = shI[32 * SH_STRIDE + 32];
                }
            }
            __syncthreads();
            // 3. stencil + pointwise update (ptxas CSEs shared loads across j)
            float nhr[4], nhi[4];
            #pragma unroll
            for (int j = 0; j < 4; j++) {
                float lapR = 0.f, lapI = 0.f;
                #pragma unroll
                for (int dr = 0; dr < 3; dr++) {
                    #pragma unroll
                    for (int dc = 0; dc < 3; dc++) {
                        float wv = w[dr * 3 + dc];
                        int off = (pr + dr) * SH_STRIDE + pcb + j + dc;
                        lapR = fmaf(wv, shR[off], lapR);
                        lapI = fmaf(wv, shI[off], lapI);
                    }
                }
                float h2 = fmaf(hr[j], hr[j], hi[j] * hi[j]);
                float rs = alpha - beta * h2;
                float f1r = ds[j] * fmaf(A, hr[j], u[j]);
                float f1i = ds[j] * (A * hi[j]);
                float sumr = f1r - dd[j] * lapI + hr[j] * rs;
                float sumi = f1i + dd[j] * lapR + hi[j] * rs;
                nhr[j] = fmaf(0.5f, sumr, hr[j]);
                nhi[j] = fmaf(0.5f, sumi, hi[j]);
            }
            #pragma unroll
            for (int j = 0; j < 4; j++) { hr[j] = nhr[j]; hi[j] = nhi[j]; }
            __syncthreads();   // protect shared before next publish
        }

        // output projection accumulate
        {
            float4 cr = *(const float4*)&g_scratch[(784 + s) * NROWS + row0 + nbase];
            float4 ci = *(const float4*)&g_scratch[(800 + s) * NROWS + row0 + nbase];
            yacc[0] = fmaf(hr[0], cr.x, fmaf(hi[0], ci.x, yacc[0]));
            yacc[1] = fmaf(hr[1], cr.y, fmaf(hi[1], ci.y, yacc[1]));
            yacc[2] = fmaf(hr[2], cr.z, fmaf(hi[2], ci.z, yacc[2]));
            yacc[3] = fmaf(hr[3], cr.w, fmaf(hi[3], ci.w, yacc[3]));
        }
    }

    // store y (B,N,D) layout
    #pragma unroll
    for (int j = 0; j < 4; j++)
        y[(row0 + nbase + j) * DIN + d] = yacc[j];
}

// ---------------- launch ----------------
extern "C" void kernel_launch(void* const* d_in, const int* in_sizes, int n_in,
                              void* d_out, int out_size) {
    const float* x      = (const float*)d_in[0];
    const float* dtsW   = (const float*)d_in[1];
    const float* dtsb   = (const float*)d_in[2];
    const float* dtdW   = (const float*)d_in[3];
    const float* dtdb   = (const float*)d_in[4];
    const float* BW     = (const float*)d_in[5];
    const float* CrW    = (const float*)d_in[6];
    const float* CiW    = (const float*)d_in[7];
    const float* Dparam = (const float*)d_in[8];
    const float* A_log  = (const float*)d_in[9];
    const float* conv_w = (const float*)d_in[10];
    const float* ralpha = (const float*)d_in[11];
    const float* rbeta  = (const float*)d_in[12];
    float* y = (float*)d_out;

    pack_kernel<<<(DIN * COLS_PAD + 255) / 256, 256>>>(dtsW, dtsb, dtdW, dtdb, BW, CrW, CiW);
    transpose_x<<<dim3(DIN / 32, NROWS / 32), dim3(32, 8)>>>(x);
    gemm_kernel<<<dim3(COLS_PAD / GBM, NROWS / GBN), 256>>>();
    ssm_kernel<<<dim3(DIN, BSZ), 256>>>(conv_w, ralpha, rbeta, Dparam, A_log, y);
}

// round 3
// speedup vs baseline: 1.0504x; 1.0504x over previous
#include <cuda_runtime.h>
#include <math.h>

#define BSZ   4
#define NTOK  1024
#define DIN   384
#define SST   16
#define NROWS 4096          // BSZ*NTOK
#define NCOLS 816           // 384 dt_s + 384 dt_d + 16 B + 16 Cr + 16 Ci
#define COLS_PAD 832        // padded to 13*64

// ---------------- static device scratch (no runtime allocation) ----------------
__device__ __align__(16) float g_wpack[DIN * COLS_PAD];    // [k][col]  1.28 MB
__device__ __align__(16) float g_bias[COLS_PAD];
__device__ __align__(16) float g_xT[DIN * NROWS];          // [d][b*1024+n] 6.3 MB
__device__ __align__(16) float g_scratch[COLS_PAD * NROWS];// [col][b*1024+n] 13.6 MB

__device__ __forceinline__ float softplusf(float z) {
    return (z > 20.f) ? z : log1pf(expf(z));
}

// ---------------- kernel 0a: pack weights k-major + bias ----------------
__global__ void pack_kernel(const float* __restrict__ dtsW, const float* __restrict__ dtsb,
                            const float* __restrict__ dtdW, const float* __restrict__ dtdb,
                            const float* __restrict__ BW,   const float* __restrict__ CrW,
                            const float* __restrict__ CiW) {
    int i = blockIdx.x * blockDim.x + threadIdx.x;
    if (i >= DIN * COLS_PAD) return;
    int k = i / COLS_PAD;
    int c = i % COLS_PAD;
    float v = 0.f;
    if      (c < 384) v = dtsW[c * DIN + k];            // row c of dt_self_W (x@W^T)
    else if (c < 768) v = dtdW[(c - 384) * DIN + k];
    else if (c < 784) v = BW [k * SST + (c - 768)];
    else if (c < 800) v = CrW[k * SST + (c - 784)];
    else if (c < 816) v = CiW[k * SST + (c - 800)];
    g_wpack[i] = v;
    if (k == 0) {
        float bv = 0.f;
        if (c < 384)      bv = dtsb[c];
        else if (c < 768) bv = dtdb[c - 384];
        g_bias[c] = bv;
    }
}

// ---------------- kernel 0b: transpose x -> xT[d][row] ----------------
__global__ void transpose_x(const float* __restrict__ x) {
    __shared__ float tile[32][33];
    int kb = blockIdx.x * 32;   // d base
    int rb = blockIdx.y * 32;   // row base
    int tx = threadIdx.x, ty = threadIdx.y;   // 32 x 8
    #pragma unroll
    for (int i = ty; i < 32; i += 8)
        tile[i][tx] = x[(rb + i) * DIN + kb + tx];
    __syncthreads();
    #pragma unroll
    for (int i = ty; i < 32; i += 8)
        g_xT[(kb + i) * NROWS + rb + tx] = tile[tx][i];
}

// ---------------- kernel 1: fused GEMM  out[c][r] = sum_k wpack[k][c] * xT[k][r] ----------------
#define GBM 64
#define GBN 128
#define GBK 16
__global__ __launch_bounds__(256) void gemm_kernel() {
    __shared__ float Ws[GBK][68];        // 16 x 64 (+pad)
    __shared__ float Xs[GBK][GBN + 4];   // 16 x 128 (+pad)
    int tid = threadIdx.x;
    int tx = tid & 15;        // row group
    int ty = tid >> 4;        // col group
    int cBase = blockIdx.x * GBM;
    int rBase = blockIdx.y * GBN;

    float acc[4][8];
    #pragma unroll
    for (int i = 0; i < 4; i++)
        #pragma unroll
        for (int j = 0; j < 8; j++) acc[i][j] = 0.f;

    for (int kB = 0; kB < DIN; kB += GBK) {
        {
            int kk = tid >> 4, cc = (tid & 15) * 4;
            float4 v = *(const float4*)&g_wpack[(kB + kk) * COLS_PAD + cBase + cc];
            *(float4*)&Ws[kk][cc] = v;
        }
        #pragma unroll
        for (int ch = 0; ch < 2; ch++) {
            int idx = tid + ch * 256;
            int kk = idx >> 5, rr = (idx & 31) * 4;
            float4 v = *(const float4*)&g_xT[(kB + kk) * NROWS + rBase + rr];
            *(float4*)&Xs[kk][rr] = v;
        }
        __syncthreads();
        #pragma unroll
        for (int kk = 0; kk < GBK; kk++) {
            float a[4], b[8];
            *(float4*)&a[0] = *(const float4*)&Ws[kk][ty * 4];
            *(float4*)&b[0] = *(const float4*)&Xs[kk][tx * 4];
            *(float4*)&b[4] = *(const float4*)&Xs[kk][64 + tx * 4];
            #pragma unroll
            for (int i = 0; i < 4; i++)
                #pragma unroll
                for (int j = 0; j < 8; j++)
                    acc[i][j] = fmaf(a[i], b[j], acc[i][j]);
        }
        __syncthreads();
    }

    #pragma unroll
    for (int i = 0; i < 4; i++) {
        int c = cBase + ty * 4 + i;
        float bv = g_bias[c];
        bool act = (c < 768);
        float o[8];
        #pragma unroll
        for (int j = 0; j < 8; j++) {
            float v = acc[i][j];
            if (act) v = fminf(softplusf(v + bv), 0.15f);
            o[j] = v;
        }
        *(float4*)&g_scratch[c * NROWS + rBase + tx * 4]      = *(float4*)&o[0];
        *(float4*)&g_scratch[c * NROWS + rBase + 64 + tx * 4] = *(float4*)&o[4];
    }
}

// ---------------- kernel 2: per-(b,d) SSM evolution, register/shuffle stencil ----------------
// 256 threads; thread owns 1 row x 4 cols. Double-buffered shared => 1 barrier per step.
// Horizontal taps: registers + lane shuffles. Vertical taps: float4 shared loads, clamped rows.
#define SHS 36   // row stride in floats: keeps float4 alignment for pcb multiples of 4
__global__ __launch_bounds__(256) void ssm_kernel(const float* __restrict__ conv_w,
                                                  const float* __restrict__ ralpha,
                                                  const float* __restrict__ rbeta,
                                                  const float* __restrict__ Dparam,
                                                  const float* __restrict__ A_log,
                                                  float* __restrict__ y) {
    __shared__ float shR[2][32][SHS];
    __shared__ float shI[2][32][SHS];

    int d = blockIdx.x;
    int b = blockIdx.y;
    int tid = threadIdx.x;
    int row   = tid >> 3;        // grid row 0..31
    int lane8 = tid & 7;         // position within row
    int pcb   = lane8 * 4;       // col base 0,4,...,28
    int nbase = row * 32 + pcb;
    int row0  = b * NTOK;

    // clamped neighbor indices (replicate padding == index clamp)
    int rm = (row > 0)  ? row - 1 : 0;
    int rp = (row < 31) ? row + 1 : 31;
    int cl = (pcb > 0)  ? pcb - 1 : 0;
    int cr = (pcb < 28) ? pcb + 4 : 31;

    float w[9];
    #pragma unroll
    for (int i = 0; i < 9; i++) w[i] = conv_w[d * 9 + i];
    float alpha = ralpha[d];
    float beta  = rbeta[d];
    float Dp    = Dparam[d];

    float xv[4], ds[4], dd[4], yacc[4];
    {
        float4 t;
        t = *(const float4*)&g_xT[d * NROWS + row0 + nbase];
        xv[0]=t.x; xv[1]=t.y; xv[2]=t.z; xv[3]=t.w;
        t = *(const float4*)&g_scratch[d * NROWS + row0 + nbase];
        ds[0]=t.x; ds[1]=t.y; ds[2]=t.z; ds[3]=t.w;
        t = *(const float4*)&g_scratch[(384 + d) * NROWS + row0 + nbase];
        dd[0]=t.x; dd[1]=t.y; dd[2]=t.z; dd[3]=t.w;
    }
    #pragma unroll
    for (int j = 0; j < 4; j++) yacc[j] = xv[j] * Dp;

    int buf = 0;
    for (int s = 0; s < SST; s++) {
        float A = -softplusf(A_log[d * SST + s]);
        float u[4], hr[4], hi[4];
        {
            float4 t = *(const float4*)&g_scratch[(768 + s) * NROWS + row0 + nbase];
            u[0]=xv[0]*t.x; u[1]=xv[1]*t.y; u[2]=xv[2]*t.z; u[3]=xv[3]*t.w;
        }
        #pragma unroll
        for (int j = 0; j < 4; j++) { hr[j] = u[j]; hi[j] = 0.f; }

        #pragma unroll
        for (int step = 0; step < 2; step++) {
            // publish own 4 values to current buffer
            *(float4*)&shR[buf][row][pcb] = make_float4(hr[0], hr[1], hr[2], hr[3]);
            *(float4*)&shI[buf][row][pcb] = make_float4(hi[0], hi[1], hi[2], hi[3]);
            __syncthreads();   // the ONLY barrier per step (double buffering covers reuse)

            // vertical neighbor rows (replicate-clamped)
            float4 tR4 = *(const float4*)&shR[buf][rm][pcb];
            float  tRl = shR[buf][rm][cl];
            float  tRr = shR[buf][rm][cr];
            float4 bR4 = *(const float4*)&shR[buf][rp][pcb];
            float  bRl = shR[buf][rp][cl];
            float  bRr = shR[buf][rp][cr];
            float4 tI4 = *(const float4*)&shI[buf][rm][pcb];
            float  tIl = shI[buf][rm][cl];
            float  tIr = shI[buf][rm][cr];
            float4 bI4 = *(const float4*)&shI[buf][rp][pcb];
            float  bIl = shI[buf][rp][cl];
            float  bIr = shI[buf][rp][cr];

            // horizontal edge taps from adjacent lanes (same warp row), clamp at grid edge
            float mRl = __shfl_up_sync(0xffffffffu,   hr[3], 1);
            float mRr = __shfl_down_sync(0xffffffffu, hr[0], 1);
            float mIl = __shfl_up_sync(0xffffffffu,   hi[3], 1);
            float mIr = __shfl_down_sync(0xffffffffu, hi[0], 1);
            if (lane8 == 0) { mRl = hr[0]; mIl = hi[0]; }
            if (lane8 == 7) { mRr = hr[3]; mIr = hi[3]; }

            float topR[6] = {tRl, tR4.x, tR4.y, tR4.z, tR4.w, tRr};
            float midR[6] = {mRl, hr[0], hr[1], hr[2], hr[3], mRr};
            float botR[6] = {bRl, bR4.x, bR4.y, bR4.z, bR4.w, bRr};
            float topI[6] = {tIl, tI4.x, tI4.y, tI4.z, tI4.w, tIr};
            float midI[6] = {mIl, hi[0], hi[1], hi[2], hi[3], mIr};
            float botI[6] = {bIl, bI4.x, bI4.y, bI4.z, bI4.w, bIr};

            float nhr[4], nhi[4];
            #pragma unroll
            for (int j = 0; j < 4; j++) {
                float lapR = w[0] * topR[j];
                lapR = fmaf(w[1], topR[j+1], lapR);
                lapR = fmaf(w[2], topR[j+2], lapR);
                lapR = fmaf(w[3], midR[j],   lapR);
                lapR = fmaf(w[4], midR[j+1], lapR);
                lapR = fmaf(w[5], midR[j+2], lapR);
                lapR = fmaf(w[6], botR[j],   lapR);
                lapR = fmaf(w[7], botR[j+1], lapR);
                lapR = fmaf(w[8], botR[j+2], lapR);
                float lapI = w[0] * topI[j];
                lapI = fmaf(w[1], topI[j+1], lapI);
                lapI = fmaf(w[2], topI[j+2], lapI);
                lapI = fmaf(w[3], midI[j],   lapI);
                lapI = fmaf(w[4], midI[j+1], lapI);
                lapI = fmaf(w[5], midI[j+2], lapI);
                lapI = fmaf(w[6], botI[j],   lapI);
                lapI = fmaf(w[7], botI[j+1], lapI);
                lapI = fmaf(w[8], botI[j+2], lapI);

                float h2 = fmaf(hr[j], hr[j], hi[j] * hi[j]);
                float rs = alpha - beta * h2;
                float f1r = ds[j] * fmaf(A, hr[j], u[j]);
                float f1i = ds[j] * (A * hi[j]);
                float sumr = f1r - dd[j] * lapI + hr[j] * rs;
                float sumi = f1i + dd[j] * lapR + hi[j] * rs;
                nhr[j] = fmaf(0.5f, sumr, hr[j]);
                nhi[j] = fmaf(0.5f, sumi, hi[j]);
            }
            #pragma unroll
            for (int j = 0; j < 4; j++) { hr[j] = nhr[j]; hi[j] = nhi[j]; }
            buf ^= 1;
        }

        // output projection accumulate
        {
            float4 crv = *(const float4*)&g_scratch[(784 + s) * NROWS + row0 + nbase];
            float4 civ = *(const float4*)&g_scratch[(800 + s) * NROWS + row0 + nbase];
            yacc[0] = fmaf(hr[0], crv.x, fmaf(hi[0], civ.x, yacc[0]));
            yacc[1] = fmaf(hr[1], crv.y, fmaf(hi[1], civ.y, yacc[1]));
            yacc[2] = fmaf(hr[2], crv.z, fmaf(hi[2], civ.z, yacc[2]));
            yacc[3] = fmaf(hr[3], crv.w, fmaf(hi[3], civ.w, yacc[3]));
        }
    }

    #pragma unroll
    for (int j = 0; j < 4; j++)
        y[(row0 + nbase + j) * DIN + d] = yacc[j];
}

// ---------------- launch ----------------
extern "C" void kernel_launch(void* const* d_in, const int* in_sizes, int n_in,
                              void* d_out, int out_size) {
    const float* x      = (const float*)d_in[0];
    const float* dtsW   = (const float*)d_in[1];
    const float* dtsb   = (const float*)d_in[2];
    const float* dtdW   = (const float*)d_in[3];
    const float* dtdb   = (const float*)d_in[4];
    const float* BW     = (const float*)d_in[5];
    const float* CrW    = (const float*)d_in[6];
    const float* CiW    = (const float*)d_in[7];
    const float* Dparam = (const float*)d_in[8];
    const float* A_log  = (const float*)d_in[9];
    const float* conv_w = (const float*)d_in[10];
    const float* ralpha = (const float*)d_in[11];
    const float* rbeta  = (const float*)d_in[12];
    float* y = (float*)d_out;

    pack_kernel<<<(DIN * COLS_PAD + 255) / 256, 256>>>(dtsW, dtsb, dtdW, dtdb, BW, CrW, CiW);
    transpose_x<<<dim3(DIN / 32, NROWS / 32), dim3(32, 8)>>>(x);
    gemm_kernel<<<dim3(COLS_PAD / GBM, NROWS / GBN), 256>>>();
    ssm_kernel<<<dim3(DIN, BSZ), 256>>>(conv_w, ralpha, rbeta, Dparam, A_log, y);
}

// round 4
// speedup vs baseline: 1.0721x; 1.0207x over previous
#include <cuda_runtime.h>
#include <math.h>

#define BSZ   4
#define NTOK  1024
#define DIN   384
#define SST   16
#define NROWS 4096
#define NCOLS 816
#define COLS_PAD 832

__device__ __align__(16) float g_wpack[DIN * COLS_PAD];
__device__ __align__(16) float g_bias[COLS_PAD];
__device__ __align__(16) float g_xT[DIN * NROWS];
__device__ __align__(16) float g_scratch[COLS_PAD * NROWS];

__device__ __forceinline__ float softplusf(float z) {
    return (z > 20.f) ? z : log1pf(expf(z));
}

// ---------------- kernel 0a: pack weights k-major + bias ----------------
__global__ void pack_kernel(const float* __restrict__ dtsW, const float* __restrict__ dtsb,
                            const float* __restrict__ dtdW, const float* __restrict__ dtdb,
                            const float* __restrict__ BW,   const float* __restrict__ CrW,
                            const float* __restrict__ CiW) {
    int i = blockIdx.x * blockDim.x + threadIdx.x;
    if (i >= DIN * COLS_PAD) return;
    int k = i / COLS_PAD;
    int c = i % COLS_PAD;
    float v = 0.f;
    if      (c < 384) v = dtsW[c * DIN + k];
    else if (c < 768) v = dtdW[(c - 384) * DIN + k];
    else if (c < 784) v = BW [k * SST + (c - 768)];
    else if (c < 800) v = CrW[k * SST + (c - 784)];
    else if (c < 816) v = CiW[k * SST + (c - 800)];
    g_wpack[i] = v;
    if (k == 0) {
        float bv = 0.f;
        if (c < 384)      bv = dtsb[c];
        else if (c < 768) bv = dtdb[c - 384];
        g_bias[c] = bv;
    }
}

// ---------------- kernel 0b: transpose x -> xT[d][row] ----------------
__global__ void transpose_x(const float* __restrict__ x) {
    __shared__ float tile[32][33];
    int kb = blockIdx.x * 32;
    int rb = blockIdx.y * 32;
    int tx = threadIdx.x, ty = threadIdx.y;
    #pragma unroll
    for (int i = ty; i < 32; i += 8)
        tile[i][tx] = x[(rb + i) * DIN + kb + tx];
    __syncthreads();
    #pragma unroll
    for (int i = ty; i < 32; i += 8)
        g_xT[(kb + i) * NROWS + rb + tx] = tile[tx][i];
}

// ---------------- kernel 1: fused GEMM ----------------
#define GBM 64
#define GBN 128
#define GBK 16
__global__ __launch_bounds__(256) void gemm_kernel() {
    __shared__ float Ws[GBK][68];
    __shared__ float Xs[GBK][GBN + 4];
    int tid = threadIdx.x;
    int tx = tid & 15;
    int ty = tid >> 4;
    int cBase = blockIdx.x * GBM;
    int rBase = blockIdx.y * GBN;

    float acc[4][8];
    #pragma unroll
    for (int i = 0; i < 4; i++)
        #pragma unroll
        for (int j = 0; j < 8; j++) acc[i][j] = 0.f;

    for (int kB = 0; kB < DIN; kB += GBK) {
        {
            int kk = tid >> 4, cc = (tid & 15) * 4;
            float4 v = *(const float4*)&g_wpack[(kB + kk) * COLS_PAD + cBase + cc];
            *(float4*)&Ws[kk][cc] = v;
        }
        #pragma unroll
        for (int ch = 0; ch < 2; ch++) {
            int idx = tid + ch * 256;
            int kk = idx >> 5, rr = (idx & 31) * 4;
            float4 v = *(const float4*)&g_xT[(kB + kk) * NROWS + rBase + rr];
            *(float4*)&Xs[kk][rr] = v;
        }
        __syncthreads();
        #pragma unroll
        for (int kk = 0; kk < GBK; kk++) {
            float a[4], bb[8];
            *(float4*)&a[0]  = *(const float4*)&Ws[kk][ty * 4];
            *(float4*)&bb[0] = *(const float4*)&Xs[kk][tx * 4];
            *(float4*)&bb[4] = *(const float4*)&Xs[kk][64 + tx * 4];
            #pragma unroll
            for (int i = 0; i < 4; i++)
                #pragma unroll
                for (int j = 0; j < 8; j++)
                    acc[i][j] = fmaf(a[i], bb[j], acc[i][j]);
        }
        __syncthreads();
    }

    #pragma unroll
    for (int i = 0; i < 4; i++) {
        int c = cBase + ty * 4 + i;
        float bv = g_bias[c];
        bool act = (c < 768);
        float o[8];
        #pragma unroll
        for (int j = 0; j < 8; j++) {
            float v = acc[i][j];
            if (act) v = fminf(softplusf(v + bv), 0.15f);
            o[j] = v;
        }
        *(float4*)&g_scratch[c * NROWS + rBase + tx * 4]      = *(float4*)&o[0];
        *(float4*)&g_scratch[c * NROWS + rBase + 64 + tx * 4] = *(float4*)&o[4];
    }
}

// ---------------- kernel 2: SSM, thread owns 2 rows x 4 cols ----------------
// 128 threads per (b,d); block of 256 processes 2 d values.
// Shared traffic per step per thread (8 px): 4 STS.128 + 4 LDS.128 + 8 LDS.32.
#define SHS 36
__global__ __launch_bounds__(256) void ssm_kernel(const float* __restrict__ conv_w,
                                                  const float* __restrict__ ralpha,
                                                  const float* __restrict__ rbeta,
                                                  const float* __restrict__ Dparam,
                                                  const float* __restrict__ A_log,
                                                  float* __restrict__ y) {
    __shared__ float shR[2][2][32][SHS];   // [half][buf][row][col]
    __shared__ float shI[2][2][32][SHS];

    int tid  = threadIdx.x;
    int half = tid >> 7;
    int t    = tid & 127;
    int d    = blockIdx.x * 2 + half;
    int b    = blockIdx.y;
    int R0   = (t >> 3) * 2;      // top row of owned pair
    int lane8 = t & 7;
    int pcb  = lane8 * 4;
    int row0 = b * NTOK;
    int n0   = R0 * 32 + pcb;
    int n1   = n0 + 32;

    int rm = (R0 > 0)      ? R0 - 1 : 0;    // halo row above
    int rp = (R0 + 2 < 32) ? R0 + 2 : 31;   // halo row below
    int cl = (pcb > 0)  ? pcb - 1 : 0;
    int cr = (pcb < 28) ? pcb + 4 : 31;

    float w[9];
    #pragma unroll
    for (int i = 0; i < 9; i++) w[i] = conv_w[d * 9 + i];
    float alpha = ralpha[d];
    float beta  = rbeta[d];
    float Dp    = Dparam[d];

    float xv[8], ds[8], dd[8], yacc[8];
    {
        float4 a = *(const float4*)&g_xT[d * NROWS + row0 + n0];
        float4 c = *(const float4*)&g_xT[d * NROWS + row0 + n1];
        xv[0]=a.x; xv[1]=a.y; xv[2]=a.z; xv[3]=a.w;
        xv[4]=c.x; xv[5]=c.y; xv[6]=c.z; xv[7]=c.w;
        a = *(const float4*)&g_scratch[d * NROWS + row0 + n0];
        c = *(const float4*)&g_scratch[d * NROWS + row0 + n1];
        ds[0]=a.x; ds[1]=a.y; ds[2]=a.z; ds[3]=a.w;
        ds[4]=c.x; ds[5]=c.y; ds[6]=c.z; ds[7]=c.w;
        a = *(const float4*)&g_scratch[(384 + d) * NROWS + row0 + n0];
        c = *(const float4*)&g_scratch[(384 + d) * NROWS + row0 + n1];
        dd[0]=a.x; dd[1]=a.y; dd[2]=a.z; dd[3]=a.w;
        dd[4]=c.x; dd[5]=c.y; dd[6]=c.z; dd[7]=c.w;
    }
    #pragma unroll
    for (int j = 0; j < 8; j++) yacc[j] = xv[j] * Dp;

    int buf = 0;
    for (int s = 0; s < SST; s++) {
        float A = -softplusf(A_log[d * SST + s]);
        float u[8], hr[8], hi[8];
        {
            float4 a = *(const float4*)&g_scratch[(768 + s) * NROWS + row0 + n0];
            float4 c = *(const float4*)&g_scratch[(768 + s) * NROWS + row0 + n1];
            u[0]=xv[0]*a.x; u[1]=xv[1]*a.y; u[2]=xv[2]*a.z; u[3]=xv[3]*a.w;
            u[4]=xv[4]*c.x; u[5]=xv[5]*c.y; u[6]=xv[6]*c.z; u[7]=xv[7]*c.w;
        }
        #pragma unroll
        for (int j = 0; j < 8; j++) { hr[j] = u[j]; hi[j] = 0.f; }

        #pragma unroll
        for (int step = 0; step < 2; step++) {
            // publish both owned rows
            *(float4*)&shR[half][buf][R0][pcb]     = make_float4(hr[0], hr[1], hr[2], hr[3]);
            *(float4*)&shR[half][buf][R0 + 1][pcb] = make_float4(hr[4], hr[5], hr[6], hr[7]);
            *(float4*)&shI[half][buf][R0][pcb]     = make_float4(hi[0], hi[1], hi[2], hi[3]);
            *(float4*)&shI[half][buf][R0 + 1][pcb] = make_float4(hi[4], hi[5], hi[6], hi[7]);
            __syncthreads();

            // halo rows from shared (replicate-clamped)
            float4 tR4 = *(const float4*)&shR[half][buf][rm][pcb];
            float  tRl = shR[half][buf][rm][cl];
            float  tRr = shR[half][buf][rm][cr];
            float4 bR4 = *(const float4*)&shR[half][buf][rp][pcb];
            float  bRl = shR[half][buf][rp][cl];
            float  bRr = shR[half][buf][rp][cr];
            float4 tI4 = *(const float4*)&shI[half][buf][rm][pcb];
            float  tIl = shI[half][buf][rm][cl];
            float  tIr = shI[half][buf][rm][cr];
            float4 bI4 = *(const float4*)&shI[half][buf][rp][pcb];
            float  bIl = shI[half][buf][rp][cl];
            float  bIr = shI[half][buf][rp][cr];

            // horizontal edge taps via shuffle (serve both owned rows)
            float r0Rl = __shfl_up_sync(0xffffffffu,   hr[3], 1);
            float r0Rr = __shfl_down_sync(0xffffffffu, hr[0], 1);
            float r1Rl = __shfl_up_sync(0xffffffffu,   hr[7], 1);
            float r1Rr = __shfl_down_sync(0xffffffffu, hr[4], 1);
            float r0Il = __shfl_up_sync(0xffffffffu,   hi[3], 1);
            float r0Ir = __shfl_down_sync(0xffffffffu, hi[0], 1);
            float r1Il = __shfl_up_sync(0xffffffffu,   hi[7], 1);
            float r1Ir = __shfl_down_sync(0xffffffffu, hi[4], 1);
            if (lane8 == 0) { r0Rl = hr[0]; r1Rl = hr[4]; r0Il = hi[0]; r1Il = hi[4]; }
            if (lane8 == 7) { r0Rr = hr[3]; r1Rr = hr[7]; r0Ir = hi[3]; r1Ir = hi[7]; }

            // 6-wide row windows
            float hTR[6] = {tRl, tR4.x, tR4.y, tR4.z, tR4.w, tRr};
            float hBR[6] = {bRl, bR4.x, bR4.y, bR4.z, bR4.w, bRr};
            float r0R[6] = {r0Rl, hr[0], hr[1], hr[2], hr[3], r0Rr};
            float r1R[6] = {r1Rl, hr[4], hr[5], hr[6], hr[7], r1Rr};
            float hTI[6] = {tIl, tI4.x, tI4.y, tI4.z, tI4.w, tIr};
            float hBI[6] = {bIl, bI4.x, bI4.y, bI4.z, bI4.w, bIr};
            float r0I[6] = {r0Il, hi[0], hi[1], hi[2], hi[3], r0Ir};
            float r1I[6] = {r1Il, hi[4], hi[5], hi[6], hi[7], r1Ir};

            float nhr[8], nhi[8];
            #pragma unroll
            for (int c = 0; c < 4; c++) {
                // ---- row 0 pixel (index c): top=hT, mid=r0, bot=r1 ----
                float lapR =      w[0] * hTR[c];
                lapR = fmaf(w[1], hTR[c+1], lapR);
                lapR = fmaf(w[2], hTR[c+2], lapR);
                lapR = fmaf(w[3], r0R[c],   lapR);
                lapR = fmaf(w[4], r0R[c+1], lapR);
                lapR = fmaf(w[5], r0R[c+2], lapR);
                lapR = fmaf(w[6], r1R[c],   lapR);
                lapR = fmaf(w[7], r1R[c+1], lapR);
                lapR = fmaf(w[8], r1R[c+2], lapR);
                float lapI =      w[0] * hTI[c];
                lapI = fmaf(w[1], hTI[c+1], lapI);
                lapI = fmaf(w[2], hTI[c+2], lapI);
                lapI = fmaf(w[3], r0I[c],   lapI);
                lapI = fmaf(w[4], r0I[c+1], lapI);
                lapI = fmaf(w[5], r0I[c+2], lapI);
                lapI = fmaf(w[6], r1I[c],   lapI);
                lapI = fmaf(w[7], r1I[c+1], lapI);
                lapI = fmaf(w[8], r1I[c+2], lapI);
                {
                    int j = c;
                    float h2 = fmaf(hr[j], hr[j], hi[j] * hi[j]);
                    float rs = alpha - beta * h2;
                    float f1r = ds[j] * fmaf(A, hr[j], u[j]);
                    float f1i = ds[j] * (A * hi[j]);
                    float sumr = f1r - dd[j] * lapI + hr[j] * rs;
                    float sumi = f1i + dd[j] * lapR + hi[j] * rs;
                    nhr[j] = fmaf(0.5f, sumr, hr[j]);
                    nhi[j] = fmaf(0.5f, sumi, hi[j]);
                }
                // ---- row 1 pixel (index 4+c): top=r0, mid=r1, bot=hB ----
                float lapR2 =      w[0] * r0R[c];
                lapR2 = fmaf(w[1], r0R[c+1], lapR2);
                lapR2 = fmaf(w[2], r0R[c+2], lapR2);
                lapR2 = fmaf(w[3], r1R[c],   lapR2);
                lapR2 = fmaf(w[4], r1R[c+1], lapR2);
                lapR2 = fmaf(w[5], r1R[c+2], lapR2);
                lapR2 = fmaf(w[6], hBR[c],   lapR2);
                lapR2 = fmaf(w[7], hBR[c+1], lapR2);
                lapR2 = fmaf(w[8], hBR[c+2], lapR2);
                float lapI2 =      w[0] * r0I[c];
                lapI2 = fmaf(w[1], r0I[c+1], lapI2);
                lapI2 = fmaf(w[2], r0I[c+2], lapI2);
                lapI2 = fmaf(w[3], r1I[c],   lapI2);
                lapI2 = fmaf(w[4], r1I[c+1], lapI2);
                lapI2 = fmaf(w[5], r1I[c+2], lapI2);
                lapI2 = fmaf(w[6], hBI[c],   lapI2);
                lapI2 = fmaf(w[7], hBI[c+1], lapI2);
                lapI2 = fmaf(w[8], hBI[c+2], lapI2);
                {
                    int j = 4 + c;
                    float h2 = fmaf(hr[j], hr[j], hi[j] * hi[j]);
                    float rs = alpha - beta * h2;
                    float f1r = ds[j] * fmaf(A, hr[j], u[j]);
                    float f1i = ds[j] * (A * hi[j]);
                    float sumr = f1r - dd[j] * lapI2 + hr[j] * rs;
                    float sumi = f1i + dd[j] * lapR2 + hi[j] * rs;
                    nhr[j] = fmaf(0.5f, sumr, hr[j]);
                    nhi[j] = fmaf(0.5f, sumi, hi[j]);
                }
            }
            #pragma unroll
            for (int j = 0; j < 8; j++) { hr[j] = nhr[j]; hi[j] = nhi[j]; }
            buf ^= 1;
        }

        // output projection accumulate
        {
            float4 c0 = *(const float4*)&g_scratch[(784 + s) * NROWS + row0 + n0];
            float4 c1 = *(const float4*)&g_scratch[(784 + s) * NROWS + row0 + n1];
            float4 i0 = *(const float4*)&g_scratch[(800 + s) * NROWS + row0 + n0];
            float4 i1 = *(const float4*)&g_scratch[(800 + s) * NROWS + row0 + n1];
            yacc[0] = fmaf(hr[0], c0.x, fmaf(hi[0], i0.x, yacc[0]));
            yacc[1] = fmaf(hr[1], c0.y, fmaf(hi[1], i0.y, yacc[1]));
            yacc[2] = fmaf(hr[2], c0.z, fmaf(hi[2], i0.z, yacc[2]));
            yacc[3] = fmaf(hr[3], c0.w, fmaf(hi[3], i0.w, yacc[3]));
            yacc[4] = fmaf(hr[4], c1.x, fmaf(hi[4], i1.x, yacc[4]));
            yacc[5] = fmaf(hr[5], c1.y, fmaf(hi[5], i1.y, yacc[5]));
            yacc[6] = fmaf(hr[6], c1.z, fmaf(hi[6], i1.z, yacc[6]));
            yacc[7] = fmaf(hr[7], c1.w, fmaf(hi[7], i1.w, yacc[7]));
        }
    }

    #pragma unroll
    for (int j = 0; j < 4; j++) {
        y[(row0 + n0 + j) * DIN + d] = yacc[j];
        y[(row0 + n1 + j) * DIN + d] = yacc[4 + j];
    }
}

// ---------------- launch ----------------
extern "C" void kernel_launch(void* const* d_in, const int* in_sizes, int n_in,
                              void* d_out, int out_size) {
    const float* x      = (const float*)d_in[0];
    const float* dtsW   = (const float*)d_in[1];
    const float* dtsb   = (const float*)d_in[2];
    const float* dtdW   = (const float*)d_in[3];
    const float* dtdb   = (const float*)d_in[4];
    const float* BW     = (const float*)d_in[5];
    const float* CrW    = (const float*)d_in[6];
    const float* CiW    = (const float*)d_in[7];
    const float* Dparam = (const float*)d_in[8];
    const float* A_log  = (const float*)d_in[9];
    const float* conv_w = (const float*)d_in[10];
    const float* ralpha = (const float*)d_in[11];
    const float* rbeta  = (const float*)d_in[12];
    float* y = (float*)d_out;

    pack_kernel<<<(DIN * COLS_PAD + 255) / 256, 256>>>(dtsW, dtsb, dtdW, dtdb, BW, CrW, CiW);
    transpose_x<<<dim3(DIN / 32, NROWS / 32), dim3(32, 8)>>>(x);
    gemm_kernel<<<dim3(COLS_PAD / GBM, NROWS / GBN), 256>>>();
    ssm_kernel<<<dim3(DIN / 2, BSZ), 256>>>(conv_w, ralpha, rbeta, Dparam, A_log, y);
}